// round 3
// baseline (speedup 1.0000x reference)
#include <cuda_runtime.h>
#include <math.h>

typedef unsigned long long u64;

#define TOKENS 1024
#define CDIM   512
#define QKVD   1536
#define NSEQ   256
#define HEADS  8
#define DH     64
#define QT     32
#define KT     64
#define EPSF   1e-6f
#define T_SMALL 0.009f

// ---------------- packed f32x2 helpers ----------------
__device__ __forceinline__ u64 pk2(float lo, float hi) {
    u64 r; asm("mov.b64 %0,{%1,%2};" : "=l"(r) : "f"(lo), "f"(hi)); return r;
}
__device__ __forceinline__ void up2(u64 v, float& lo, float& hi) {
    asm("mov.b64 {%0,%1},%2;" : "=f"(lo), "=f"(hi) : "l"(v));
}
__device__ __forceinline__ u64 fadd2(u64 a, u64 b) {
    u64 r; asm("add.rn.f32x2 %0,%1,%2;" : "=l"(r) : "l"(a), "l"(b)); return r;
}
__device__ __forceinline__ u64 fmul2(u64 a, u64 b) {
    u64 r; asm("mul.rn.f32x2 %0,%1,%2;" : "=l"(r) : "l"(a), "l"(b)); return r;
}
__device__ __forceinline__ u64 ffma2(u64 a, u64 b, u64 c) {
    u64 r; asm("fma.rn.f32x2 %0,%1,%2,%3;" : "=l"(r) : "l"(a), "l"(b), "l"(c)); return r;
}

// ---------------- device scratch ----------------
__device__ float g_qkv[TOKENS * QKVD];
__device__ float g_att[TOKENS * CDIM];
__device__ float g_qs [TOKENS * CDIM];
__device__ float g_qc [TOKENS * CDIM];
__device__ float g_knv[TOKENS * CDIM];   // -k
__device__ float g_kns[TOKENS * CDIM];   // -sin(R k)
__device__ float g_kc [TOKENS * CDIM];   //  cos(R k)

// ---------------------------------------------------------------------------
// Trig precompute over q,k halves of qkv.
// ---------------------------------------------------------------------------
__global__ __launch_bounds__(256)
void trig_prep(const float* __restrict__ qkv, const float* __restrict__ paramR,
               float* __restrict__ gqs, float* __restrict__ gqc,
               float* __restrict__ gknv, float* __restrict__ gkns,
               float* __restrict__ gkc)
{
    int i = blockIdx.x * 256 + threadIdx.x;
    const float R = paramR[0];
    int tok = i >> 9, col = i & 511;
    float qv = qkv[tok * QKVD + col];
    float s, c;
    sincosf(R * qv, &s, &c);
    gqs[i] = s; gqc[i] = c;
    float kv = qkv[tok * QKVD + CDIM + col];
    sincosf(R * kv, &s, &c);
    gknv[i] = -kv; gkns[i] = -s; gkc[i] = c;
}

// ---------------------------------------------------------------------------
// f32x2 SGEMM, MOV-free inner loop.
// C[M,Ncols] = A[M,K]*Bw[Ncols,K]^T (+bias). Tile BM x 64, BK=16, 128 threads.
// Per thread: (2*MP) M-rows (as MP f32x2 pairs) x 4 N-cols.
// A pairs adjacent in As rows -> LDS.128 straight to u64 pairs.
// B duplicated {b,b} in Bs -> LDS.128 gives packed operands directly.
// ---------------------------------------------------------------------------
template<int BM>
__global__ __launch_bounds__(128)
void sgemm2(const float* __restrict__ A, const float* __restrict__ Bw,
            const float* __restrict__ bias, float* __restrict__ C,
            int Ncols, int K)
{
    __shared__ __align__(16) float  As[16][BM];
    __shared__ __align__(16) float2 Bs[16][64];
    const int t  = threadIdx.x;
    const int m0 = blockIdx.y * BM;
    const int n0 = blockIdx.x * 64;
    const int tx = t & 15, ty = t >> 4;
    constexpr int MP = BM / 16;           // m-pairs per thread (4 or 2)
    const int mr = ty * 2 * MP;
    const int n4 = tx * 4;
    constexpr int AF4 = BM / 32;          // A float4 loads per thread (2 or 1)

    u64 acc[MP][4];
    #pragma unroll
    for (int i = 0; i < MP; i++)
        #pragma unroll
        for (int j = 0; j < 4; j++) acc[i][j] = 0ull;

    float4 pa[AF4], pb[2];
    const int nit = K / 16;

    #pragma unroll
    for (int v = 0; v < AF4; v++) {
        int f4 = t + v * 128; int m = f4 >> 2, kq = (f4 & 3) << 2;
        pa[v] = *(const float4*)&A[(m0 + m) * K + kq];
    }
    #pragma unroll
    for (int v = 0; v < 2; v++) {
        int f4 = t + v * 128; int n = f4 >> 2, kq = (f4 & 3) << 2;
        pb[v] = *(const float4*)&Bw[(n0 + n) * K + kq];
    }

    for (int it = 0; it < nit; ++it) {
        #pragma unroll
        for (int v = 0; v < AF4; v++) {
            int f4 = t + v * 128; int m = f4 >> 2, kq = (f4 & 3) << 2;
            As[kq+0][m] = pa[v].x; As[kq+1][m] = pa[v].y;
            As[kq+2][m] = pa[v].z; As[kq+3][m] = pa[v].w;
        }
        #pragma unroll
        for (int v = 0; v < 2; v++) {
            int f4 = t + v * 128; int n = f4 >> 2, kq = (f4 & 3) << 2;
            Bs[kq+0][n] = make_float2(pb[v].x, pb[v].x);
            Bs[kq+1][n] = make_float2(pb[v].y, pb[v].y);
            Bs[kq+2][n] = make_float2(pb[v].z, pb[v].z);
            Bs[kq+3][n] = make_float2(pb[v].w, pb[v].w);
        }
        __syncthreads();
        if (it + 1 < nit) {
            int k0 = (it + 1) * 16;
            #pragma unroll
            for (int v = 0; v < AF4; v++) {
                int f4 = t + v * 128; int m = f4 >> 2, kq = (f4 & 3) << 2;
                pa[v] = *(const float4*)&A[(m0 + m) * K + k0 + kq];
            }
            #pragma unroll
            for (int v = 0; v < 2; v++) {
                int f4 = t + v * 128; int n = f4 >> 2, kq = (f4 & 3) << 2;
                pb[v] = *(const float4*)&Bw[(n0 + n) * K + k0 + kq];
            }
        }
        #pragma unroll
        for (int k = 0; k < 16; ++k) {
            u64 a2[MP], b2[4];
            const ulonglong2* ap = (const ulonglong2*)&As[k][mr];
            #pragma unroll
            for (int i = 0; i < MP / 2; i++) {
                ulonglong2 v = ap[i]; a2[2*i] = v.x; a2[2*i+1] = v.y;
            }
            const ulonglong2* bp = (const ulonglong2*)&Bs[k][n4];
            {
                ulonglong2 v0 = bp[0], v1 = bp[1];
                b2[0] = v0.x; b2[1] = v0.y; b2[2] = v1.x; b2[3] = v1.y;
            }
            #pragma unroll
            for (int mp = 0; mp < MP; mp++)
                #pragma unroll
                for (int nn = 0; nn < 4; nn++)
                    acc[mp][nn] = ffma2(a2[mp], b2[nn], acc[mp][nn]);
        }
        __syncthreads();
    }

    float bb0 = 0.f, bb1 = 0.f, bb2 = 0.f, bb3 = 0.f;
    if (bias) {
        float4 bv = *(const float4*)&bias[n0 + n4];
        bb0 = bv.x; bb1 = bv.y; bb2 = bv.z; bb3 = bv.w;
    }
    #pragma unroll
    for (int mp = 0; mp < MP; mp++) {
        int r0 = m0 + mr + 2 * mp;
        float lo0, hi0, lo1, hi1, lo2, hi2, lo3, hi3;
        up2(acc[mp][0], lo0, hi0); up2(acc[mp][1], lo1, hi1);
        up2(acc[mp][2], lo2, hi2); up2(acc[mp][3], lo3, hi3);
        float4 o0 = make_float4(lo0 + bb0, lo1 + bb1, lo2 + bb2, lo3 + bb3);
        float4 o1 = make_float4(hi0 + bb0, hi1 + bb1, hi2 + bb2, hi3 + bb3);
        *(float4*)&C[(size_t)r0 * Ncols + n0 + n4]       = o0;
        *(float4*)&C[(size_t)(r0 + 1) * Ncols + n0 + n4] = o1;
    }
}

// ---------------------------------------------------------------------------
// Fourier attention. Block = (qtile, head, batch), 256 threads.
// q = tid&31 (query lane), kg = tid>>5 (8 keys per group).
// f32x2 for diff / cross-product / sin (operands straight from smem u64),
// scalar selects + scalar product chains (validated order-0 small case).
// ---------------------------------------------------------------------------
#define PADQ 66
static const int ATTN_SMEM = (3 * QT * PADQ + 3 * KT * DH + NSEQ * QT + 8 * QT + QT) * 4;

__global__ __launch_bounds__(256, 2)
void fourier_attn2(const float* __restrict__ qkv,
                   const float* __restrict__ gqs, const float* __restrict__ gqc,
                   const float* __restrict__ gknv, const float* __restrict__ gkns,
                   const float* __restrict__ gkc,
                   const float* __restrict__ paramR, float* __restrict__ attout)
{
    extern __shared__ float sm[];
    float* sQv = sm;                     // [32][66]
    float* sQs = sQv + QT * PADQ;
    float* sQc = sQs + QT * PADQ;
    float* sKv = sQc + QT * PADQ;        // [64][64]
    float* sKs = sKv + KT * DH;
    float* sKc = sKs + KT * DH;
    float* sS  = sKc + KT * DH;          // [256][32]
    float* sRed = sS + NSEQ * QT;        // [8][32]
    float* sInv = sRed + 8 * QT;         // [32]

    const int tid = threadIdx.x;
    const int q = tid & 31, kg = tid >> 5;
    const int qt = blockIdx.x, h = blockIdx.y, b = blockIdx.z;
    const int tok0 = b * NSEQ, q0 = qt * QT;
    const float R = paramR[0];

    // q-side fill (pure copies from precomputed trig)
    for (int i = tid; i < QT * 32; i += 256) {
        int qq = i >> 5, d2 = i & 31;
        int g = (tok0 + q0 + qq) * CDIM + h * DH + d2 * 2;
        int sidx = qq * PADQ + d2 * 2;
        *(float2*)&sQs[sidx] = *(const float2*)&gqs[g];
        *(float2*)&sQc[sidx] = *(const float2*)&gqc[g];
        *(float2*)&sQv[sidx] = *(const float2*)&qkv[(tok0 + q0 + qq) * QKVD + h * DH + d2 * 2];
    }

    for (int kc0 = 0; kc0 < NSEQ; kc0 += KT) {
        __syncthreads();
        for (int i = tid; i < KT * 16; i += 256) {
            int kk = i >> 4, dq = (i & 15) * 4;
            int g = (tok0 + kc0 + kk) * CDIM + h * DH + dq;
            int sidx = kk * DH + dq;
            *(float4*)&sKv[sidx] = *(const float4*)&gknv[g];
            *(float4*)&sKs[sidx] = *(const float4*)&gkns[g];
            *(float4*)&sKc[sidx] = *(const float4*)&gkc[g];
        }
        __syncthreads();

        float np[8], dp[8];
        #pragma unroll
        for (int j = 0; j < 8; j++) { np[j] = 1.f; dp[j] = 1.f; }
        const int kb0 = kg * 8 * DH;

        #pragma unroll 4
        for (int d2 = 0; d2 < 32; d2++) {
            u64 qv2 = *(const u64*)&sQv[q * PADQ + d2 * 2];
            u64 qs2 = *(const u64*)&sQs[q * PADQ + d2 * 2];
            u64 qc2 = *(const u64*)&sQc[q * PADQ + d2 * 2];
            #pragma unroll
            for (int j = 0; j < 8; j++) {
                int kidx = kb0 + j * DH + d2 * 2;
                u64 kv2 = *(const u64*)&sKv[kidx];
                u64 ks2 = *(const u64*)&sKs[kidx];
                u64 kc2 = *(const u64*)&sKc[kidx];
                u64 diff2 = fadd2(qv2, kv2);                   // q - k
                u64 num2  = ffma2(qs2, kc2, fmul2(qc2, ks2));  // sin(R(q-k))
                float d0, d1, n0v, n1v;
                up2(diff2, d0, d1); up2(num2, n0v, n1v);
                bool s0 = fabsf(d0) < T_SMALL, s1 = fabsf(d1) < T_SMALL;
                np[j] *= s0 ? R : n0v;
                dp[j] *= s0 ? 1.f : d0;
                np[j] *= s1 ? R : n1v;
                dp[j] *= s1 ? 1.f : d1;
            }
        }
        #pragma unroll
        for (int j = 0; j < 8; j++) {
            float s = (dp[j] != 0.f) ? np[j] / dp[j] : 0.f;
            float s2 = s * s;
            sS[(kc0 + kg * 8 + j) * QT + q] = s2 * s2;
        }
    }
    __syncthreads();

    // row sums
    {
        float part = 0.f;
        #pragma unroll 8
        for (int j = kg * 32; j < kg * 32 + 32; j++) part += sS[j * QT + q];
        sRed[kg * QT + q] = part;
    }
    __syncthreads();
    if (kg == 0) {
        float ss = 0.f;
        #pragma unroll
        for (int r = 0; r < 8; r++) ss += sRed[r * QT + q];
        sInv[q] = 1.f / (ss + EPSF);
    }

    // PV: packed over dim pairs, V loaded directly as u64 from smem
    u64 acc[4];
    #pragma unroll
    for (int i = 0; i < 4; i++) acc[i] = 0ull;
    for (int kc0 = 0; kc0 < NSEQ; kc0 += KT) {
        __syncthreads();
        for (int i = tid; i < KT * 16; i += 256) {
            int kk = i >> 4, dq = (i & 15) * 4;
            *(float4*)&sKv[kk * DH + dq] =
                *(const float4*)&qkv[(tok0 + kc0 + kk) * QKVD + 2 * CDIM + h * DH + dq];
        }
        __syncthreads();
        #pragma unroll 4
        for (int jj = 0; jj < KT; jj++) {
            float a = sS[(kc0 + jj) * QT + q];
            u64 a2 = pk2(a, a);
            const ulonglong2* vp = (const ulonglong2*)&sKv[jj * DH + kg * 8];
            ulonglong2 v0 = vp[0], v1 = vp[1];
            acc[0] = ffma2(a2, v0.x, acc[0]);
            acc[1] = ffma2(a2, v0.y, acc[1]);
            acc[2] = ffma2(a2, v1.x, acc[2]);
            acc[3] = ffma2(a2, v1.y, acc[3]);
        }
    }
    float rinv = sInv[q];
    float o[8];
    up2(acc[0], o[0], o[1]); up2(acc[1], o[2], o[3]);
    up2(acc[2], o[4], o[5]); up2(acc[3], o[6], o[7]);
    float4 w0 = make_float4(o[0] * rinv, o[1] * rinv, o[2] * rinv, o[3] * rinv);
    float4 w1 = make_float4(o[4] * rinv, o[5] * rinv, o[6] * rinv, o[7] * rinv);
    float* dst = &attout[(tok0 + q0 + q) * CDIM + h * DH + kg * 8];
    *(float4*)dst       = w0;
    *(float4*)(dst + 4) = w1;
}

extern "C" void kernel_launch(void* const* d_in, const int* in_sizes, int n_in,
                              void* d_out, int out_size)
{
    const float* x      = (const float*)d_in[0];
    const float* w_qkv  = (const float*)d_in[1];
    const float* w_proj = (const float*)d_in[2];
    const float* b_proj = (const float*)d_in[3];
    const float* paramR = (const float*)d_in[4];
    float* out = (float*)d_out;

    float *qkvbuf, *attbuf, *gqs, *gqc, *gknv, *gkns, *gkc;
    cudaGetSymbolAddress((void**)&qkvbuf, g_qkv);
    cudaGetSymbolAddress((void**)&attbuf, g_att);
    cudaGetSymbolAddress((void**)&gqs,  g_qs);
    cudaGetSymbolAddress((void**)&gqc,  g_qc);
    cudaGetSymbolAddress((void**)&gknv, g_knv);
    cudaGetSymbolAddress((void**)&gkns, g_kns);
    cudaGetSymbolAddress((void**)&gkc,  g_kc);

    cudaFuncSetAttribute(fourier_attn2, cudaFuncAttributeMaxDynamicSharedMemorySize,
                         ATTN_SMEM);

    // 1) qkv = x @ w_qkv^T   (1024 x 1536, K=512): 64x64 tiles -> 384 blocks
    sgemm2<64><<<dim3(QKVD / 64, TOKENS / 64), 128>>>(x, w_qkv, nullptr,
                                                      qkvbuf, QKVD, CDIM);
    // 2) trig precompute
    trig_prep<<<TOKENS * CDIM / 256, 256>>>(qkvbuf, paramR, gqs, gqc, gknv, gkns, gkc);
    // 3) attention core (256 blocks, all co-resident)
    fourier_attn2<<<dim3(NSEQ / QT, HEADS, 4), 256, ATTN_SMEM>>>(
        qkvbuf, gqs, gqc, gknv, gkns, gkc, paramR, attbuf);
    // 4) out = att @ w_proj^T + b_proj: 32x64 tiles -> 256 blocks
    sgemm2<32><<<dim3(CDIM / 64, TOKENS / 32), 128>>>(attbuf, w_proj, b_proj,
                                                      out, CDIM, CDIM);
}

// round 4
// speedup vs baseline: 1.3760x; 1.3760x over previous
#include <cuda_runtime.h>
#include <math.h>

typedef unsigned long long u64;

#define TOKENS 1024
#define CDIM   512
#define QKVD   1536
#define NSEQ   256
#define HEADS  8
#define DH     64
#define QT     32
#define KT     64
#define EPSF   1e-6f
#define T_SMALL 0.009f
#define PADQ   66

// ---------------- packed f32x2 helpers ----------------
__device__ __forceinline__ u64 pk2(float lo, float hi) {
    u64 r; asm("mov.b64 %0,{%1,%2};" : "=l"(r) : "f"(lo), "f"(hi)); return r;
}
__device__ __forceinline__ void up2(u64 v, float& lo, float& hi) {
    asm("mov.b64 {%0,%1},%2;" : "=f"(lo), "=f"(hi) : "l"(v));
}
__device__ __forceinline__ u64 fadd2(u64 a, u64 b) {
    u64 r; asm("add.rn.f32x2 %0,%1,%2;" : "=l"(r) : "l"(a), "l"(b)); return r;
}
__device__ __forceinline__ u64 fmul2(u64 a, u64 b) {
    u64 r; asm("mul.rn.f32x2 %0,%1,%2;" : "=l"(r) : "l"(a), "l"(b)); return r;
}
__device__ __forceinline__ u64 ffma2(u64 a, u64 b, u64 c) {
    u64 r; asm("fma.rn.f32x2 %0,%1,%2,%3;" : "=l"(r) : "l"(a), "l"(b), "l"(c)); return r;
}

// ---------------- device scratch ----------------
__device__ float g_qkv[TOKENS * QKVD];
__device__ float g_att[TOKENS * CDIM];
__device__ float g_qs [TOKENS * CDIM];
__device__ float g_qc [TOKENS * CDIM];
__device__ float g_knv[TOKENS * CDIM];   // -k
__device__ float g_kns[TOKENS * CDIM];   // -sin(R k)
__device__ float g_kc [TOKENS * CDIM];   //  cos(R k)

// ---------------------------------------------------------------------------
// Trig precompute over q,k halves of qkv.
// ---------------------------------------------------------------------------
__global__ __launch_bounds__(256)
void trig_prep(const float* __restrict__ qkv, const float* __restrict__ paramR,
               float* __restrict__ gqs, float* __restrict__ gqc,
               float* __restrict__ gknv, float* __restrict__ gkns,
               float* __restrict__ gkc)
{
    int i = blockIdx.x * 256 + threadIdx.x;
    const float R = paramR[0];
    int tok = i >> 9, col = i & 511;
    float qv = qkv[tok * QKVD + col];
    float s, c;
    sincosf(R * qv, &s, &c);
    gqs[i] = s; gqc[i] = c;
    float kv = qkv[tok * QKVD + CDIM + col];
    sincosf(R * kv, &s, &c);
    gknv[i] = -kv; gkns[i] = -s; gkc[i] = c;
}

// ---------------------------------------------------------------------------
// FFMA2 GEMM: C[M,Ncols] = A[M,K]*Bw[Ncols,K]^T (+bias).
// BM=64, BK=16, 256 threads. Per thread: 4 M-rows (2 f32x2 pairs) x TN N-cols.
// A pairs adjacent in As rows -> one LDS.128 per k, broadcast across warp.
// B scalar in smem; packed to {b,b} with one MOV each.
// ---------------------------------------------------------------------------
template<int BN, int TN>
__global__ __launch_bounds__(256)
void gemm2f(const float* __restrict__ A, const float* __restrict__ Bw,
            const float* __restrict__ bias, float* __restrict__ C,
            int Ncols, int K)
{
    __shared__ __align__(16) float As[16][68];
    __shared__ __align__(16) float Bs[16][BN + 4];
    const int t  = threadIdx.x;
    const int m0 = blockIdx.y * 64;
    const int n0 = blockIdx.x * BN;
    const int tx = t & 15, ty = t >> 4;

    u64 acc[2][TN];
    #pragma unroll
    for (int p = 0; p < 2; p++)
        #pragma unroll
        for (int n = 0; n < TN; n++) acc[p][n] = 0ull;

    const int am = t >> 2, akq = (t & 3) << 2;       // A: 1 float4 / thread
    const int bn4 = t >> 2, bkq = (t & 3) << 2;      // B loads (BN=64 case)
    const int bn2 = t >> 3, bkp = (t & 7) << 1;      // B loads (BN=32 case)

    float4 pa, pb4; float2 pb2;
    pa = *(const float4*)&A[(m0 + am) * K + akq];
    if (TN == 4) pb4 = *(const float4*)&Bw[(n0 + bn4) * K + bkq];
    else         pb2 = *(const float2*)&Bw[(n0 + bn2) * K + bkp];

    const int nit = K / 16;
    for (int it = 0; it < nit; ++it) {
        As[akq + 0][am] = pa.x; As[akq + 1][am] = pa.y;
        As[akq + 2][am] = pa.z; As[akq + 3][am] = pa.w;
        if (TN == 4) {
            Bs[bkq + 0][bn4] = pb4.x; Bs[bkq + 1][bn4] = pb4.y;
            Bs[bkq + 2][bn4] = pb4.z; Bs[bkq + 3][bn4] = pb4.w;
        } else {
            Bs[bkp + 0][bn2] = pb2.x; Bs[bkp + 1][bn2] = pb2.y;
        }
        __syncthreads();
        if (it + 1 < nit) {
            int k0 = (it + 1) * 16;
            pa = *(const float4*)&A[(m0 + am) * K + k0 + akq];
            if (TN == 4) pb4 = *(const float4*)&Bw[(n0 + bn4) * K + k0 + bkq];
            else         pb2 = *(const float2*)&Bw[(n0 + bn2) * K + k0 + bkp];
        }
        #pragma unroll
        for (int k = 0; k < 16; ++k) {
            ulonglong2 av = *(const ulonglong2*)&As[k][ty << 2];
            if (TN == 4) {
                float4 bv = *(const float4*)&Bs[k][tx << 2];
                u64 b0 = pk2(bv.x, bv.x), b1 = pk2(bv.y, bv.y);
                u64 b2 = pk2(bv.z, bv.z), b3 = pk2(bv.w, bv.w);
                acc[0][0] = ffma2(av.x, b0, acc[0][0]);
                acc[0][1] = ffma2(av.x, b1, acc[0][1]);
                acc[0][2] = ffma2(av.x, b2, acc[0][2]);
                acc[0][3] = ffma2(av.x, b3, acc[0][3]);
                acc[1][0] = ffma2(av.y, b0, acc[1][0]);
                acc[1][1] = ffma2(av.y, b1, acc[1][1]);
                acc[1][2] = ffma2(av.y, b2, acc[1][2]);
                acc[1][3] = ffma2(av.y, b3, acc[1][3]);
            } else {
                float2 bv = *(const float2*)&Bs[k][tx << 1];
                u64 b0 = pk2(bv.x, bv.x), b1 = pk2(bv.y, bv.y);
                acc[0][0] = ffma2(av.x, b0, acc[0][0]);
                acc[0][1] = ffma2(av.x, b1, acc[0][1]);
                acc[1][0] = ffma2(av.y, b0, acc[1][0]);
                acc[1][1] = ffma2(av.y, b1, acc[1][1]);
            }
        }
        __syncthreads();
    }

    float bb[TN];
    #pragma unroll
    for (int n = 0; n < TN; n++) bb[n] = bias ? bias[n0 + tx * TN + n] : 0.f;

    #pragma unroll
    for (int p = 0; p < 2; p++) {
        int r0 = m0 + (ty << 2) + 2 * p;
        float lo[TN], hi[TN];
        #pragma unroll
        for (int n = 0; n < TN; n++) up2(acc[p][n], lo[n], hi[n]);
        if (TN == 4) {
            float4 o0 = make_float4(lo[0] + bb[0], lo[1] + bb[1], lo[2] + bb[2], lo[3] + bb[3]);
            float4 o1 = make_float4(hi[0] + bb[0], hi[1] + bb[1], hi[2] + bb[2], hi[3] + bb[3]);
            *(float4*)&C[(size_t)r0 * Ncols + n0 + tx * 4]       = o0;
            *(float4*)&C[(size_t)(r0 + 1) * Ncols + n0 + tx * 4] = o1;
        } else {
            float2 o0 = make_float2(lo[0] + bb[0], lo[1] + bb[1]);
            float2 o1 = make_float2(hi[0] + bb[0], hi[1] + bb[1]);
            *(float2*)&C[(size_t)r0 * Ncols + n0 + tx * 2]       = o0;
            *(float2*)&C[(size_t)(r0 + 1) * Ncols + n0 + tx * 2] = o1;
        }
    }
}

// ---------------------------------------------------------------------------
// Fused Fourier attention: score + online PV in one pass (no 32KB score buf).
// Block = (qtile, head, batch), 256 threads. q = tid&31, kg = tid>>5.
// Thread (q,kg) handles keys kg*8..+8 over ALL 64 dims (32 u64 accumulators),
// then cross-warp reduction through the freed K-region smem.
// ---------------------------------------------------------------------------
#define KREG 17408                       // [8][32][68] acc region (>= 4*4096)
static const int ATTN_SMEM = (3 * QT * PADQ + KREG + 8 * QT + QT) * 4;

__global__ __launch_bounds__(256, 2)
void fourier_attn3(const float* __restrict__ qkv,
                   const float* __restrict__ gqs, const float* __restrict__ gqc,
                   const float* __restrict__ gknv, const float* __restrict__ gkns,
                   const float* __restrict__ gkc,
                   const float* __restrict__ paramR, float* __restrict__ attout)
{
    extern __shared__ float sm[];
    float* sQv = sm;                      // [32][66]
    float* sQs = sQv + QT * PADQ;
    float* sQc = sQs + QT * PADQ;
    float* smK = sQc + QT * PADQ;         // tile region / later acc region
    float* sKv = smK;                     // [64][64]
    float* sKs = smK + 4096;
    float* sKc = smK + 8192;
    float* sV  = smK + 12288;
    float* sRed = smK + KREG;             // [8][32]

    const int tid = threadIdx.x;
    const int q = tid & 31, kg = tid >> 5;
    const int qt = blockIdx.x, h = blockIdx.y, b = blockIdx.z;
    const int tok0 = b * NSEQ, q0 = qt * QT;
    const float R = paramR[0];

    // q-side fill (pure copies from precomputed trig)
    for (int i = tid; i < QT * 32; i += 256) {
        int qq = i >> 5, d2 = i & 31;
        int g = (tok0 + q0 + qq) * CDIM + h * DH + d2 * 2;
        int sidx = qq * PADQ + d2 * 2;
        *(float2*)&sQs[sidx] = *(const float2*)&gqs[g];
        *(float2*)&sQc[sidx] = *(const float2*)&gqc[g];
        *(float2*)&sQv[sidx] = *(const float2*)&qkv[(tok0 + q0 + qq) * QKVD + h * DH + d2 * 2];
    }

    u64 acc[32];
    #pragma unroll
    for (int i = 0; i < 32; i++) acc[i] = 0ull;
    float rowsum = 0.f;

    for (int kc0 = 0; kc0 < NSEQ; kc0 += KT) {
        __syncthreads();
        for (int i = tid; i < KT * 16; i += 256) {
            int kk = i >> 4, dq = (i & 15) * 4;
            int g = (tok0 + kc0 + kk) * CDIM + h * DH + dq;
            int sidx = kk * DH + dq;
            *(float4*)&sKv[sidx] = *(const float4*)&gknv[g];
            *(float4*)&sKs[sidx] = *(const float4*)&gkns[g];
            *(float4*)&sKc[sidx] = *(const float4*)&gkc[g];
            *(float4*)&sV[sidx]  = *(const float4*)&qkv[(tok0 + kc0 + kk) * QKVD + 2 * CDIM + h * DH + dq];
        }
        __syncthreads();

        // ---- score for this thread's 8 keys ----
        float np[8], dp[8];
        #pragma unroll
        for (int j = 0; j < 8; j++) { np[j] = 1.f; dp[j] = 1.f; }
        const int kb0 = kg * 8 * DH;

        #pragma unroll 4
        for (int d2 = 0; d2 < 32; d2++) {
            u64 qv2 = *(const u64*)&sQv[q * PADQ + d2 * 2];
            u64 qs2 = *(const u64*)&sQs[q * PADQ + d2 * 2];
            u64 qc2 = *(const u64*)&sQc[q * PADQ + d2 * 2];
            #pragma unroll
            for (int j = 0; j < 8; j++) {
                int kidx = kb0 + j * DH + d2 * 2;
                u64 kv2 = *(const u64*)&sKv[kidx];
                u64 ks2 = *(const u64*)&sKs[kidx];
                u64 kc2 = *(const u64*)&sKc[kidx];
                u64 diff2 = fadd2(qv2, kv2);                   // q - k
                u64 num2  = ffma2(qs2, kc2, fmul2(qc2, ks2));  // sin(R(q-k))
                float d0, d1, n0v, n1v;
                up2(diff2, d0, d1); up2(num2, n0v, n1v);
                bool s0 = fabsf(d0) < T_SMALL, s1 = fabsf(d1) < T_SMALL;
                np[j] *= s0 ? R : n0v;
                dp[j] *= s0 ? 1.f : d0;
                np[j] *= s1 ? R : n1v;
                dp[j] *= s1 ? 1.f : d1;
            }
        }

        // ---- a4 + online PV over this thread's keys, all 64 dims ----
        #pragma unroll
        for (int j = 0; j < 8; j++) {
            float s = (dp[j] != 0.f) ? np[j] / dp[j] : 0.f;
            float s2 = s * s;
            float a4 = s2 * s2;
            rowsum += a4;
            u64 aa = pk2(a4, a4);
            const ulonglong2* vp = (const ulonglong2*)&sV[(kg * 8 + j) * DH];
            #pragma unroll
            for (int w = 0; w < 16; w++) {
                ulonglong2 vv = vp[w];                         // warp-uniform
                acc[2 * w]     = ffma2(aa, vv.x, acc[2 * w]);
                acc[2 * w + 1] = ffma2(aa, vv.y, acc[2 * w + 1]);
            }
        }
    }
    __syncthreads();

    // stash partials: rowsum and 64-dim acc into freed K region
    sRed[kg * 32 + q] = rowsum;
    {
        float* myAcc = &smK[(kg * 32 + q) * 68];
        #pragma unroll
        for (int w = 0; w < 16; w++) {
            ulonglong2 vv; vv.x = acc[2 * w]; vv.y = acc[2 * w + 1];
            *(ulonglong2*)&myAcc[w * 4] = vv;
        }
    }
    __syncthreads();

    // normalization factor
    float ss = 0.f;
    #pragma unroll
    for (int r = 0; r < 8; r++) ss += sRed[r * 32 + q];
    float inv = 1.f / (ss + EPSF);
    u64 inv2 = pk2(inv, inv);

    // cross-warp reduce: thread (q,kg) produces dims kg*8..+8
    u64 o[4];
    #pragma unroll
    for (int i = 0; i < 4; i++) o[i] = 0ull;
    #pragma unroll
    for (int kgp = 0; kgp < 8; kgp++) {
        const float* src = &smK[(kgp * 32 + q) * 68 + kg * 8];
        ulonglong2 v0 = *(const ulonglong2*)src;
        ulonglong2 v1 = *(const ulonglong2*)(src + 4);
        o[0] = fadd2(o[0], v0.x); o[1] = fadd2(o[1], v0.y);
        o[2] = fadd2(o[2], v1.x); o[3] = fadd2(o[3], v1.y);
    }
    #pragma unroll
    for (int i = 0; i < 4; i++) o[i] = fmul2(o[i], inv2);

    float of[8];
    up2(o[0], of[0], of[1]); up2(o[1], of[2], of[3]);
    up2(o[2], of[4], of[5]); up2(o[3], of[6], of[7]);
    float* dst = &attout[(tok0 + q0 + q) * CDIM + h * DH + kg * 8];
    *(float4*)dst       = make_float4(of[0], of[1], of[2], of[3]);
    *(float4*)(dst + 4) = make_float4(of[4], of[5], of[6], of[7]);
}

extern "C" void kernel_launch(void* const* d_in, const int* in_sizes, int n_in,
                              void* d_out, int out_size)
{
    const float* x      = (const float*)d_in[0];
    const float* w_qkv  = (const float*)d_in[1];
    const float* w_proj = (const float*)d_in[2];
    const float* b_proj = (const float*)d_in[3];
    const float* paramR = (const float*)d_in[4];
    float* out = (float*)d_out;

    float *qkvbuf, *attbuf, *gqs, *gqc, *gknv, *gkns, *gkc;
    cudaGetSymbolAddress((void**)&qkvbuf, g_qkv);
    cudaGetSymbolAddress((void**)&attbuf, g_att);
    cudaGetSymbolAddress((void**)&gqs,  g_qs);
    cudaGetSymbolAddress((void**)&gqc,  g_qc);
    cudaGetSymbolAddress((void**)&gknv, g_knv);
    cudaGetSymbolAddress((void**)&gkns, g_kns);
    cudaGetSymbolAddress((void**)&gkc,  g_kc);

    cudaFuncSetAttribute(fourier_attn3, cudaFuncAttributeMaxDynamicSharedMemorySize,
                         ATTN_SMEM);

    // 1) qkv = x @ w_qkv^T (1024x1536, K=512): 64x64 tiles -> 384 blocks, 256 thr
    gemm2f<64, 4><<<dim3(QKVD / 64, TOKENS / 64), 256>>>(x, w_qkv, nullptr,
                                                         qkvbuf, QKVD, CDIM);
    // 2) trig precompute
    trig_prep<<<TOKENS * CDIM / 256, 256>>>(qkvbuf, paramR, gqs, gqc, gknv, gkns, gkc);
    // 3) fused attention (256 blocks, 2/SM resident -> single wave)
    fourier_attn3<<<dim3(NSEQ / QT, HEADS, 4), 256, ATTN_SMEM>>>(
        qkvbuf, gqs, gqc, gknv, gkns, gkc, paramR, attbuf);
    // 4) out = att @ w_proj^T + b_proj: 64x32 tiles -> 256 blocks, 256 thr
    gemm2f<32, 2><<<dim3(CDIM / 32, TOKENS / 64), 256>>>(attbuf, w_proj, b_proj,
                                                         out, CDIM, CDIM);
}